// round 16
// baseline (speedup 1.0000x reference)
#include <cuda_runtime.h>
#include <cuda_bf16.h>
#include <math.h>
#include <float.h>
#include <stdint.h>

#define BATCH 256
#define NEXP  200000
#define DIM   128
#define DS    96
#define DA    32

#define TILE_N   128
#define NTILES   1563                 // ceil(200000/128)
#define STILES   98
#define SAMPLE_N (STILES * TILE_N)    // 12544
#define SRANK    63                   // 0-based sample rank for threshold
#define MAXC     2048                 // per-agent candidate buffer

#define PITCH 136                     // bf16 elems per smem row (128 + 8 pad)

// ---------------- static device scratch ----------------
__device__ float          g_a2w[BATCH];
__device__ float          g_inv[DIM];                    // 1/std^2
__device__ __nv_bfloat16  g_abf[BATCH * DIM];            // (a/s^2) in bf16
__device__ float          g_d2s[(size_t)BATCH * SAMPLE_N];  // row-major [b][i]
__device__ float          g_thresh[BATCH];
__device__ int            g_cnt[BATCH];
__device__ float          g_cand2[(size_t)BATCH * MAXC];

// ---------------- helpers ----------------
__device__ __forceinline__ uint32_t smem_u32(const void* p) {
    uint32_t a;
    asm("{ .reg .u64 t; cvta.to.shared.u64 t, %1; cvt.u32.u64 %0, t; }" : "=r"(a) : "l"(p));
    return a;
}
__device__ __forceinline__ void ldm_x4(uint32_t& r0, uint32_t& r1, uint32_t& r2, uint32_t& r3,
                                       uint32_t addr) {
    asm volatile("ldmatrix.sync.aligned.m8n8.x4.shared.b16 {%0,%1,%2,%3}, [%4];"
                 : "=r"(r0), "=r"(r1), "=r"(r2), "=r"(r3) : "r"(addr));
}
__device__ __forceinline__ void mma_bf16(float* d, const uint32_t* a, const uint32_t* b) {
    asm volatile("mma.sync.aligned.m16n8k16.row.col.f32.bf16.bf16.f32 "
                 "{%0,%1,%2,%3}, {%4,%5,%6,%7}, {%8,%9}, {%0,%1,%2,%3};"
                 : "+f"(d[0]), "+f"(d[1]), "+f"(d[2]), "+f"(d[3])
                 : "r"(a[0]), "r"(a[1]), "r"(a[2]), "r"(a[3]), "r"(b[0]), "r"(b[1]));
}
__device__ __forceinline__ uint32_t bf2u(float lo, float hi) {
    __nv_bfloat162 b = __floats2bfloat162_rn(lo, hi);
    return *reinterpret_cast<uint32_t*>(&b);
}

// radix pass for 256-thread blocks (final_kernel)
__device__ __forceinline__ void radix_pass(unsigned int* hist, unsigned int* s_pref,
                                           int* s_rank, int t) {
    __shared__ unsigned int wsum[8];
    const int lane = t & 31, wp = t >> 5;
    unsigned int v = hist[t];
    unsigned int inc = v;
    #pragma unroll
    for (int o = 1; o < 32; o <<= 1) {
        unsigned int u = __shfl_up_sync(0xffffffffu, inc, o);
        if (lane >= o) inc += u;
    }
    if (lane == 31) wsum[wp] = inc;
    __syncthreads();
    unsigned int base = 0;
    #pragma unroll
    for (int i = 0; i < 8; i++) if (i < wp) base += wsum[i];
    const unsigned int incl = inc + base;
    const unsigned int excl = incl - v;
    const int r = *s_rank;
    __syncthreads();
    if ((unsigned)r >= excl && (unsigned)r < incl) {
        *s_rank = r - (int)excl;
        *s_pref = (*s_pref << 8) | (unsigned)t;
    }
    __syncthreads();
}

// radix pass for 512-thread blocks (thresh_kernel); bins handled by warps 0-7
__device__ __forceinline__ void radix_pass512(unsigned int* hist, unsigned int* s_pref,
                                              int* s_rank, int t) {
    __shared__ unsigned int wsum[8];
    const int lane = t & 31, wp = t >> 5;
    unsigned int v = 0, inc = 0;
    if (wp < 8) {
        v = hist[t];
        inc = v;
        #pragma unroll
        for (int o = 1; o < 32; o <<= 1) {
            unsigned int u = __shfl_up_sync(0xffffffffu, inc, o);
            if (lane >= o) inc += u;
        }
        if (lane == 31) wsum[wp] = inc;
    }
    __syncthreads();
    unsigned int base = 0;
    if (wp < 8) {
        #pragma unroll
        for (int i = 0; i < 8; i++) if (i < wp) base += wsum[i];
    }
    const unsigned int incl = inc + base;
    const unsigned int excl = incl - v;
    const int r = *s_rank;
    __syncthreads();
    if (wp < 8 && (unsigned)r >= excl && (unsigned)r < incl) {
        *s_rank = r - (int)excl;
        *s_pref = (*s_pref << 8) | (unsigned)t;
    }
    __syncthreads();
}

// ---------------- K0: agent prep (also zeroes candidate counters) ----------
__global__ void prep_agent_kernel(const float* __restrict__ state,
                                  const float* __restrict__ action,
                                  const float* __restrict__ sstd) {
    __shared__ float red[DIM];
    int b = blockIdx.x, d = threadIdx.x;
    float a = (d < DS) ? state[b * DS + d] : action[b * DA + (d - DS)];
    float s = sstd[d];
    float inv = 1.0f / (s * s);
    float awv = a * inv;
    g_abf[b * DIM + d] = __float2bfloat16_rn(awv);
    if (b == 0) g_inv[d] = inv;
    if (d == 0) g_cnt[b] = 0;
    red[d] = awv * a;
    __syncthreads();
    for (int off = 64; off > 0; off >>= 1) {
        if (d < off) red[d] += red[d + off];
        __syncthreads();
    }
    if (d == 0) g_a2w[b] = red[0];
}

// ---------------- K2: HMMA bf16 GEMM, full M=256 per CTA ----------------
// 256 threads, 8 warps (4M x 2N), warp tile 32x64, two A-half passes
// smem layout (bytes)
#define OFF_A    0                              // 256*272 = 69632
#define OFF_B    69632                          // 128*272 = 34816
#define OFF_E2   104448                         // 128*4
#define GEMM_SMEM 104960

__global__ void __launch_bounds__(256, 2)
gemm_kernel(const float* __restrict__ experts, int mode, int tile_base) {
    extern __shared__ __align__(16) char sm[];
    const uint32_t smb = smem_u32(sm);
    const int tid = threadIdx.x, w = tid >> 5, lane = tid & 31;
    const int tile = blockIdx.x + tile_base;
    const int n0 = tile * TILE_N;

    float* e2s = (float*)(sm + OFF_E2);

    // ---- A tile (bf16, 256 rows): 2 threads/row, 128B each, 2 passes ----
    #pragma unroll
    for (int it = 0; it < 2; it++) {
        int r = it * 128 + (tid >> 1), h = (tid & 1) * 8;
        const uint4* asrc = (const uint4*)(g_abf + (size_t)r * DIM) + h;
        uint4* adst = (uint4*)(sm + OFF_A + r * PITCH * 2 + h * 16);
        #pragma unroll
        for (int i = 0; i < 8; i++) adst[i] = asrc[i];
    }

    // ---- E tile (128 rows): coalesced fp32 -> bf16 + per-row weighted norm ----
    {
        const int lane8 = lane & 7, lrow = lane >> 3;   // col group, row-in-4
        #pragma unroll
        for (int it = 0; it < 4; it++) {
            const int r = it * 32 + w * 4 + lrow;
            const int n = n0 + r;
            const bool ok = (n < NEXP);
            const float* src = experts + (size_t)n * DIM;
            float part = 0.f;
            #pragma unroll
            for (int s = 0; s < 4; s++) {
                const int cf = s * 32 + lane8 * 4;
                float4 f = ok ? __ldg((const float4*)(src + cf)) : make_float4(0.f, 0.f, 0.f, 0.f);
                const float4 wv = __ldg((const float4*)(g_inv + cf));
                part += f.x * f.x * wv.x + f.y * f.y * wv.y + f.z * f.z * wv.z + f.w * f.w * wv.w;
                uint2 o = make_uint2(bf2u(f.x, f.y), bf2u(f.z, f.w));
                *(uint2*)(sm + OFF_B + (r * PITCH + cf) * 2) = o;
            }
            part += __shfl_xor_sync(0xffffffffu, part, 1);
            part += __shfl_xor_sync(0xffffffffu, part, 2);
            part += __shfl_xor_sync(0xffffffffu, part, 4);
            if (lane8 == 0) e2s[r] = ok ? part : 1e30f;
        }
    }
    __syncthreads();

    // ---- warp tile: 32 (M) x 64 (N); warps 4 (M) x 2 (N); 2 A-half passes ----
    const int mbase = (w >> 1) * 32, nbase = (w & 1) * 64;
    const int c0 = nbase + (lane & 3) * 2;

    const uint32_t b_addr0 = smb + OFF_B +
        (uint32_t)(((nbase + (lane >> 4) * 8 + (lane & 7)) * PITCH + ((lane >> 3) & 1) * 8) * 2);

    #pragma unroll
    for (int ah = 0; ah < 2; ah++) {
        const uint32_t a_addr0 = smb + OFF_A +
            (uint32_t)(((ah * 128 + mbase + (lane & 15)) * PITCH + (lane >> 4) * 8) * 2);

        float acc[2][8][4];
        #pragma unroll
        for (int mf = 0; mf < 2; mf++)
            #pragma unroll
            for (int j = 0; j < 8; j++)
                #pragma unroll
                for (int q = 0; q < 4; q++) acc[mf][j][q] = 0.f;

        #pragma unroll
        for (int k = 0; k < 8; k++) {
            const uint32_t koff = (uint32_t)(k * 32);   // 16 bf16 = 32B
            uint32_t A[2][4];
            ldm_x4(A[0][0], A[0][1], A[0][2], A[0][3], a_addr0 + koff);
            ldm_x4(A[1][0], A[1][1], A[1][2], A[1][3], a_addr0 + koff + 16 * PITCH * 2);
            uint32_t Bf[8][2];
            #pragma unroll
            for (int jj = 0; jj < 4; jj++) {
                uint32_t r0, r1, r2, r3;
                ldm_x4(r0, r1, r2, r3, b_addr0 + koff + (uint32_t)(jj * 16 * PITCH * 2));
                Bf[jj * 2][0] = r0; Bf[jj * 2][1] = r1;
                Bf[jj * 2 + 1][0] = r2; Bf[jj * 2 + 1][1] = r3;
            }
            #pragma unroll
            for (int mf = 0; mf < 2; mf++)
                #pragma unroll
                for (int j = 0; j < 8; j++)
                    mma_bf16(acc[mf][j], A[mf], Bf[j]);
        }

        // ---- epilogue for this half ----
        #pragma unroll
        for (int mf = 0; mf < 2; mf++) {
            #pragma unroll
            for (int hr = 0; hr < 2; hr++) {
                const int agent = ah * 128 + mbase + mf * 16 + (lane >> 2) + hr * 8;
                const float a2 = __ldg(g_a2w + agent);
                if (mode == 0) {
                    float* dst = g_d2s + (size_t)agent * SAMPLE_N + n0;
                    #pragma unroll
                    for (int j = 0; j < 8; j++) {
                        const int col = c0 + j * 8;
                        float d2a = fmaxf(a2 + e2s[col]     - 2.0f * acc[mf][j][hr * 2],     1e-12f);
                        float d2b = fmaxf(a2 + e2s[col + 1] - 2.0f * acc[mf][j][hr * 2 + 1], 1e-12f);
                        *(float2*)(dst + col) = make_float2(d2a, d2b);
                    }
                } else {
                    const float T = __ldg(g_thresh + agent);
                    #pragma unroll
                    for (int j = 0; j < 8; j++) {
                        const int col = c0 + j * 8;
                        float d2a = fmaxf(a2 + e2s[col]     - 2.0f * acc[mf][j][hr * 2],     1e-12f);
                        float d2b = fmaxf(a2 + e2s[col + 1] - 2.0f * acc[mf][j][hr * 2 + 1], 1e-12f);
                        if (d2a < T) {
                            int p = atomicAdd(&g_cnt[agent], 1);
                            if (p < MAXC) g_cand2[(size_t)agent * MAXC + p] = d2a;
                        }
                        if (d2b < T) {
                            int p = atomicAdd(&g_cnt[agent], 1);
                            if (p < MAXC) g_cand2[(size_t)agent * MAXC + p] = d2b;
                        }
                    }
                }
            }
        }
    }
}

// ---------------- K3: sample threshold + harvest sample candidates ----------
__global__ void __launch_bounds__(512) thresh_kernel() {
    extern __shared__ float sv[];  // SAMPLE_N floats
    __shared__ unsigned int hist[256];
    __shared__ unsigned int s_pref;
    __shared__ int s_rank;
    const int b = blockIdx.x, t = threadIdx.x;
    {
        const float4* src = (const float4*)(g_d2s + (size_t)b * SAMPLE_N);
        float4* dst = (float4*)sv;
        for (int i = t; i < SAMPLE_N / 4; i += 512) dst[i] = src[i];
    }
    if (t == 0) { s_pref = 0u; s_rank = SRANK; }
    __syncthreads();
    for (int pass = 3; pass >= 0; pass--) {
        int shift = pass * 8;
        if (t < 256) hist[t] = 0u;
        __syncthreads();
        unsigned int pref = s_pref;
        for (int i = t; i < SAMPLE_N; i += 512) {
            unsigned int key = __float_as_uint(sv[i]);
            if (((key >> shift) >> 8) == pref)
                atomicAdd(&hist[(key >> shift) & 255u], 1u);
        }
        __syncthreads();
        radix_pass512(hist, &s_pref, &s_rank, t);
    }
    const unsigned int Tkey = s_pref;
    if (t == 0) g_thresh[b] = __uint_as_float(Tkey);
    // harvest: sample region == population tiles [0, STILES); append d2 < T
    for (int i = t; i < SAMPLE_N; i += 512) {
        float v = sv[i];
        if (__float_as_uint(v) < Tkey) {
            int p = atomicAdd(&g_cnt[b], 1);
            if (p < MAXC) g_cand2[(size_t)b * MAXC + p] = v;
        }
    }
}

// ---------------- K4: final exact select over candidate list + reward -------
__global__ void __launch_bounds__(256) final_kernel(const float* __restrict__ wts,
                                                    float* __restrict__ out) {
    __shared__ float sv[MAXC];
    __shared__ unsigned int hist[256];
    __shared__ unsigned int s_pref;
    __shared__ int s_rank;
    __shared__ float s_f[256];
    __shared__ int s_i[256];
    __shared__ float s_w;
    __shared__ double s_r;
    __shared__ int s_m;
    const int b = blockIdx.x, t = threadIdx.x;

    const int cnt = min(g_cnt[b], MAXC);
    for (int i = t; i < cnt; i += 256) sv[i] = g_cand2[(size_t)b * MAXC + i];

    if (t == 0) {
        float w = wts[0];
        double targ = 1.0 / 1000.0 - 1e-6;
        int m = (int)(targ / (double)w);
        double r = targ - (double)m * (double)w;
        if (r <= 0.0) { m -= 1; r = (double)w; }
        s_w = w; s_m = m; s_r = r;
        s_pref = 0u; s_rank = (m < cnt) ? m : (cnt - 1);
    }
    __syncthreads();

    for (int pass = 3; pass >= 0; pass--) {
        int shift = pass * 8;
        hist[t] = 0u;
        __syncthreads();
        unsigned int pref = s_pref;
        for (int i = t; i < cnt; i += 256) {
            unsigned int key = __float_as_uint(sv[i]);
            if (((key >> shift) >> 8) == pref)
                atomicAdd(&hist[(key >> shift) & 255u], 1u);
        }
        __syncthreads();
        radix_pass(hist, &s_pref, &s_rank, t);
    }

    unsigned int Tkey = s_pref;
    float Tval = __uint_as_float(Tkey);
    int c = 0;
    float ss = 0.0f;
    for (int i = t; i < cnt; i += 256) {
        float v = sv[i];
        if (__float_as_uint(v) < Tkey) { c++; ss += sqrtf(v); }
    }
    s_f[t] = ss; s_i[t] = c;
    __syncthreads();
    for (int off = 128; off > 0; off >>= 1) {
        if (t < off) { s_f[t] += s_f[t + off]; s_i[t] += s_i[t + off]; }
        __syncthreads();
    }
    if (t == 0) {
        double w = (double)s_w;
        double dT = sqrt((double)Tval);
        double cost = w * (double)s_f[0] + (w * (double)(s_m - s_i[0]) + s_r) * dT;
        double BW = 5000.0 / sqrt(128.0);
        out[b] = (float)(5.0 * exp(-BW * cost));
    }
}

// ---------------- launch ----------------
extern "C" void kernel_launch(void* const* d_in, const int* in_sizes, int n_in,
                              void* d_out, int out_size) {
    const float* state   = (const float*)d_in[0];
    const float* action  = (const float*)d_in[1];
    const float* experts = (const float*)d_in[2];
    const float* wts     = (const float*)d_in[3];
    // d_in[4] = scaler_mean: cancels algebraically
    const float* sstd    = (const float*)d_in[5];
    float* out = (float*)d_out;

    cudaFuncSetAttribute(gemm_kernel,   cudaFuncAttributeMaxDynamicSharedMemorySize, GEMM_SMEM);
    cudaFuncSetAttribute(thresh_kernel, cudaFuncAttributeMaxDynamicSharedMemorySize, SAMPLE_N * 4);

    prep_agent_kernel<<<BATCH, DIM>>>(state, action, sstd);
    gemm_kernel<<<STILES, 256, GEMM_SMEM>>>(experts, 0, 0);
    thresh_kernel<<<BATCH, 512, SAMPLE_N * 4>>>();
    gemm_kernel<<<NTILES - STILES, 256, GEMM_SMEM>>>(experts, 1, STILES);
    final_kernel<<<BATCH, 256>>>(wts, out);
}

// round 17
// speedup vs baseline: 1.2585x; 1.2585x over previous
#include <cuda_runtime.h>
#include <cuda_bf16.h>
#include <math.h>
#include <float.h>
#include <stdint.h>

#define BATCH 256
#define NEXP  200000
#define DIM   128
#define DS    96
#define DA    32

#define TILE_N   128
#define NTILES   1563                 // ceil(200000/128)
#define STILES   98
#define SAMPLE_N (STILES * TILE_N)    // 12544
#define SRANK    63                   // 0-based sample rank for threshold
#define SLOTS    12                   // smem slots per agent per tile
#define MAXC     2048                 // per-agent compact candidate buffer

#define PITCH 136                     // bf16 elems per smem row (128 + 8 pad)

// ---------------- static device scratch ----------------
__device__ float          g_a2w[BATCH];
__device__ float          g_inv[DIM];                    // 1/std^2
__device__ __nv_bfloat16  g_abf[BATCH * DIM];            // (a/s^2) in bf16
__device__ float          g_d2s[(size_t)BATCH * SAMPLE_N];  // row-major [b][i]
__device__ float          g_thresh[BATCH];
__device__ int            g_cnt[BATCH];
__device__ float          g_cand2[(size_t)BATCH * MAXC];

// ---------------- helpers ----------------
__device__ __forceinline__ uint32_t smem_u32(const void* p) {
    uint32_t a;
    asm("{ .reg .u64 t; cvta.to.shared.u64 t, %1; cvt.u32.u64 %0, t; }" : "=r"(a) : "l"(p));
    return a;
}
__device__ __forceinline__ void ldm_x4(uint32_t& r0, uint32_t& r1, uint32_t& r2, uint32_t& r3,
                                       uint32_t addr) {
    asm volatile("ldmatrix.sync.aligned.m8n8.x4.shared.b16 {%0,%1,%2,%3}, [%4];"
                 : "=r"(r0), "=r"(r1), "=r"(r2), "=r"(r3) : "r"(addr));
}
__device__ __forceinline__ void mma_bf16(float* d, const uint32_t* a, const uint32_t* b) {
    asm volatile("mma.sync.aligned.m16n8k16.row.col.f32.bf16.bf16.f32 "
                 "{%0,%1,%2,%3}, {%4,%5,%6,%7}, {%8,%9}, {%0,%1,%2,%3};"
                 : "+f"(d[0]), "+f"(d[1]), "+f"(d[2]), "+f"(d[3])
                 : "r"(a[0]), "r"(a[1]), "r"(a[2]), "r"(a[3]), "r"(b[0]), "r"(b[1]));
}
__device__ __forceinline__ uint32_t bf2u(float lo, float hi) {
    __nv_bfloat162 b = __floats2bfloat162_rn(lo, hi);
    return *reinterpret_cast<uint32_t*>(&b);
}

// radix pass for 256-thread blocks (final_kernel)
__device__ __forceinline__ void radix_pass(unsigned int* hist, unsigned int* s_pref,
                                           int* s_rank, int t) {
    __shared__ unsigned int wsum[8];
    const int lane = t & 31, wp = t >> 5;
    unsigned int v = hist[t];
    unsigned int inc = v;
    #pragma unroll
    for (int o = 1; o < 32; o <<= 1) {
        unsigned int u = __shfl_up_sync(0xffffffffu, inc, o);
        if (lane >= o) inc += u;
    }
    if (lane == 31) wsum[wp] = inc;
    __syncthreads();
    unsigned int base = 0;
    #pragma unroll
    for (int i = 0; i < 8; i++) if (i < wp) base += wsum[i];
    const unsigned int incl = inc + base;
    const unsigned int excl = incl - v;
    const int r = *s_rank;
    __syncthreads();
    if ((unsigned)r >= excl && (unsigned)r < incl) {
        *s_rank = r - (int)excl;
        *s_pref = (*s_pref << 8) | (unsigned)t;
    }
    __syncthreads();
}

// radix pass for 512-thread blocks (thresh_kernel); bins handled by warps 0-7
__device__ __forceinline__ void radix_pass512(unsigned int* hist, unsigned int* s_pref,
                                              int* s_rank, int t) {
    __shared__ unsigned int wsum[8];
    const int lane = t & 31, wp = t >> 5;
    unsigned int v = 0, inc = 0;
    if (wp < 8) {
        v = hist[t];
        inc = v;
        #pragma unroll
        for (int o = 1; o < 32; o <<= 1) {
            unsigned int u = __shfl_up_sync(0xffffffffu, inc, o);
            if (lane >= o) inc += u;
        }
        if (lane == 31) wsum[wp] = inc;
    }
    __syncthreads();
    unsigned int base = 0;
    if (wp < 8) {
        #pragma unroll
        for (int i = 0; i < 8; i++) if (i < wp) base += wsum[i];
    }
    const unsigned int incl = inc + base;
    const unsigned int excl = incl - v;
    const int r = *s_rank;
    __syncthreads();
    if (wp < 8 && (unsigned)r >= excl && (unsigned)r < incl) {
        *s_rank = r - (int)excl;
        *s_pref = (*s_pref << 8) | (unsigned)t;
    }
    __syncthreads();
}

// ---------------- K0: agent prep (also zeroes candidate counters) ----------
__global__ void prep_agent_kernel(const float* __restrict__ state,
                                  const float* __restrict__ action,
                                  const float* __restrict__ sstd) {
    __shared__ float red[DIM];
    int b = blockIdx.x, d = threadIdx.x;
    float a = (d < DS) ? state[b * DS + d] : action[b * DA + (d - DS)];
    float s = sstd[d];
    float inv = 1.0f / (s * s);
    float awv = a * inv;
    g_abf[b * DIM + d] = __float2bfloat16_rn(awv);
    if (b == 0) g_inv[d] = inv;
    if (d == 0) g_cnt[b] = 0;
    red[d] = awv * a;
    __syncthreads();
    for (int off = 64; off > 0; off >>= 1) {
        if (d < off) red[d] += red[d + off];
        __syncthreads();
    }
    if (d == 0) g_a2w[b] = red[0];
}

// ---------------- K2: HMMA bf16 GEMM (mode 0: sample d2, mode 1: filtered) ----
// 256 threads, 8 warps (4M x 2N), warp tile 32x64, CTA tile 128 x 128 (R8 shape)
// epilogue: smem slots (fast ATOMS), then compact flush (1 global atomic/agent)
// smem layout (bytes)
#define OFF_A    0                              // 128*272 = 34816
#define OFF_B    34816                          // 128*272 = 34816
#define OFF_E2   69632                          // 128*4
#define OFF_A2   70144
#define OFF_TH   70656
#define OFF_CNT  71168
#define OFF_INV  71680
#define OFF_CAND 72192                          // 128*12*4 = 6144
#define GEMM_SMEM 78336

__global__ void __launch_bounds__(256, 2)
gemm_kernel(const float* __restrict__ experts, int mode, int tile_base) {
    extern __shared__ __align__(16) char sm[];
    const uint32_t smb = smem_u32(sm);
    const int tid = threadIdx.x, w = tid >> 5, lane = tid & 31;
    const int hid = blockIdx.x;                // agent half: 0 or 1
    const int tile = blockIdx.y + tile_base;
    const int n0 = tile * TILE_N;

    float* e2s  = (float*)(sm + OFF_E2);
    float* a2s  = (float*)(sm + OFF_A2);
    float* ths  = (float*)(sm + OFF_TH);
    int*   scnt = (int*)(sm + OFF_CNT);
    float* sinv = (float*)(sm + OFF_INV);
    float* scand = (float*)(sm + OFF_CAND);

    if (tid < 128) {
        sinv[tid] = g_inv[tid];
        a2s[tid] = g_a2w[hid * 128 + tid];
        ths[tid] = g_thresh[hid * 128 + tid];
        scnt[tid] = 0;
    }

    // ---- A tile (bf16, 128 rows): 2 threads/row, 128B each ----
    {
        int r = tid >> 1, h = (tid & 1) * 8;
        const uint4* asrc = (const uint4*)(g_abf + (size_t)(hid * 128 + r) * DIM) + h;
        uint4* adst = (uint4*)(sm + OFF_A + r * PITCH * 2 + h * 16);
        #pragma unroll
        for (int i = 0; i < 8; i++) adst[i] = asrc[i];
    }
    __syncthreads();   // sinv ready before E loader uses it

    // ---- E tile (128 rows): coalesced fp32 -> bf16 + per-row weighted norm ----
    {
        const int lane8 = lane & 7, lrow = lane >> 3;   // col group, row-in-4
        #pragma unroll
        for (int it = 0; it < 4; it++) {
            const int r = it * 32 + w * 4 + lrow;
            const int n = n0 + r;
            const bool ok = (n < NEXP);
            const float* src = experts + (size_t)n * DIM;
            float part = 0.f;
            #pragma unroll
            for (int s = 0; s < 4; s++) {
                const int cf = s * 32 + lane8 * 4;
                float4 f = ok ? __ldg((const float4*)(src + cf)) : make_float4(0.f, 0.f, 0.f, 0.f);
                const float4 wv = *(const float4*)(sinv + cf);
                part += f.x * f.x * wv.x + f.y * f.y * wv.y + f.z * f.z * wv.z + f.w * f.w * wv.w;
                uint2 o = make_uint2(bf2u(f.x, f.y), bf2u(f.z, f.w));
                *(uint2*)(sm + OFF_B + (r * PITCH + cf) * 2) = o;
            }
            part += __shfl_xor_sync(0xffffffffu, part, 1);
            part += __shfl_xor_sync(0xffffffffu, part, 2);
            part += __shfl_xor_sync(0xffffffffu, part, 4);
            if (lane8 == 0) e2s[r] = ok ? part : 1e30f;
        }
    }
    __syncthreads();

    // ---- warp tile: 32 (M) x 64 (N); warps 4 (M) x 2 (N) ----
    const int mbase = (w >> 1) * 32, nbase = (w & 1) * 64;
    const int c0 = nbase + (lane & 3) * 2;

    const uint32_t a_addr0 = smb + OFF_A +
        (uint32_t)(((mbase + (lane & 15)) * PITCH + (lane >> 4) * 8) * 2);
    const uint32_t b_addr0 = smb + OFF_B +
        (uint32_t)(((nbase + (lane >> 4) * 8 + (lane & 7)) * PITCH + ((lane >> 3) & 1) * 8) * 2);

    float acc[2][8][4];
    #pragma unroll
    for (int mf = 0; mf < 2; mf++)
        #pragma unroll
        for (int j = 0; j < 8; j++)
            #pragma unroll
            for (int q = 0; q < 4; q++) acc[mf][j][q] = 0.f;

    #pragma unroll
    for (int k = 0; k < 8; k++) {
        const uint32_t koff = (uint32_t)(k * 32);   // 16 bf16 = 32B
        uint32_t A[2][4];
        ldm_x4(A[0][0], A[0][1], A[0][2], A[0][3], a_addr0 + koff);
        ldm_x4(A[1][0], A[1][1], A[1][2], A[1][3], a_addr0 + koff + 16 * PITCH * 2);
        uint32_t Bf[8][2];
        #pragma unroll
        for (int jj = 0; jj < 4; jj++) {
            uint32_t r0, r1, r2, r3;
            ldm_x4(r0, r1, r2, r3, b_addr0 + koff + (uint32_t)(jj * 16 * PITCH * 2));
            Bf[jj * 2][0] = r0; Bf[jj * 2][1] = r1;
            Bf[jj * 2 + 1][0] = r2; Bf[jj * 2 + 1][1] = r3;
        }
        #pragma unroll
        for (int mf = 0; mf < 2; mf++)
            #pragma unroll
            for (int j = 0; j < 8; j++)
                mma_bf16(acc[mf][j], A[mf], Bf[j]);
    }

    // ---- epilogue ----
    #pragma unroll
    for (int mf = 0; mf < 2; mf++) {
        #pragma unroll
        for (int hr = 0; hr < 2; hr++) {
            const int rl = mbase + mf * 16 + (lane >> 2) + hr * 8;   // local agent row
            const float a2 = a2s[rl];
            const int agent = hid * 128 + rl;
            if (mode == 0) {
                float* dst = g_d2s + (size_t)agent * SAMPLE_N + n0;
                #pragma unroll
                for (int j = 0; j < 8; j++) {
                    const int col = c0 + j * 8;
                    float d2a = fmaxf(a2 + e2s[col]     - 2.0f * acc[mf][j][hr * 2],     1e-12f);
                    float d2b = fmaxf(a2 + e2s[col + 1] - 2.0f * acc[mf][j][hr * 2 + 1], 1e-12f);
                    *(float2*)(dst + col) = make_float2(d2a, d2b);
                }
            } else {
                const float T = ths[rl];
                #pragma unroll
                for (int j = 0; j < 8; j++) {
                    const int col = c0 + j * 8;
                    float d2a = fmaxf(a2 + e2s[col]     - 2.0f * acc[mf][j][hr * 2],     1e-12f);
                    float d2b = fmaxf(a2 + e2s[col + 1] - 2.0f * acc[mf][j][hr * 2 + 1], 1e-12f);
                    if (d2a < T) { int p = atomicAdd(&scnt[rl], 1); if (p < SLOTS) scand[rl * SLOTS + p] = d2a; }
                    if (d2b < T) { int p = atomicAdd(&scnt[rl], 1); if (p < SLOTS) scand[rl * SLOTS + p] = d2b; }
                }
            }
        }
    }

    if (mode == 1) {
        __syncthreads();
        // compact flush: one global atomic per agent with hits, then copy
        if (tid < 128) {
            const int agent = hid * 128 + tid;
            int c = min(scnt[tid], SLOTS);
            if (c > 0) {
                int base = atomicAdd(&g_cnt[agent], c);
                for (int i = 0; i < c; i++) {
                    int p = base + i;
                    if (p < MAXC) g_cand2[(size_t)agent * MAXC + p] = scand[tid * SLOTS + i];
                }
            }
        }
    }
}

// ---------------- K3: sample threshold + harvest sample candidates ----------
__global__ void __launch_bounds__(512) thresh_kernel() {
    extern __shared__ float sv[];  // SAMPLE_N floats
    __shared__ unsigned int hist[256];
    __shared__ unsigned int s_pref;
    __shared__ int s_rank;
    const int b = blockIdx.x, t = threadIdx.x;
    {
        const float4* src = (const float4*)(g_d2s + (size_t)b * SAMPLE_N);
        float4* dst = (float4*)sv;
        for (int i = t; i < SAMPLE_N / 4; i += 512) dst[i] = src[i];
    }
    if (t == 0) { s_pref = 0u; s_rank = SRANK; }
    __syncthreads();
    for (int pass = 3; pass >= 0; pass--) {
        int shift = pass * 8;
        if (t < 256) hist[t] = 0u;
        __syncthreads();
        unsigned int pref = s_pref;
        for (int i = t; i < SAMPLE_N; i += 512) {
            unsigned int key = __float_as_uint(sv[i]);
            if (((key >> shift) >> 8) == pref)
                atomicAdd(&hist[(key >> shift) & 255u], 1u);
        }
        __syncthreads();
        radix_pass512(hist, &s_pref, &s_rank, t);
    }
    const unsigned int Tkey = s_pref;
    if (t == 0) g_thresh[b] = __uint_as_float(Tkey);
    // harvest: sample region == population tiles [0, STILES); append d2 < T
    for (int i = t; i < SAMPLE_N; i += 512) {
        float v = sv[i];
        if (__float_as_uint(v) < Tkey) {
            int p = atomicAdd(&g_cnt[b], 1);
            if (p < MAXC) g_cand2[(size_t)b * MAXC + p] = v;
        }
    }
}

// ---------------- K4: final exact select over candidate list + reward -------
__global__ void __launch_bounds__(256) final_kernel(const float* __restrict__ wts,
                                                    float* __restrict__ out) {
    __shared__ float sv[MAXC];
    __shared__ unsigned int hist[256];
    __shared__ unsigned int s_pref;
    __shared__ int s_rank;
    __shared__ float s_f[256];
    __shared__ int s_i[256];
    __shared__ float s_w;
    __shared__ double s_r;
    __shared__ int s_m;
    const int b = blockIdx.x, t = threadIdx.x;

    const int cnt = min(g_cnt[b], MAXC);
    for (int i = t; i < cnt; i += 256) sv[i] = g_cand2[(size_t)b * MAXC + i];

    if (t == 0) {
        float w = wts[0];
        double targ = 1.0 / 1000.0 - 1e-6;
        int m = (int)(targ / (double)w);
        double r = targ - (double)m * (double)w;
        if (r <= 0.0) { m -= 1; r = (double)w; }
        s_w = w; s_m = m; s_r = r;
        s_pref = 0u; s_rank = (m < cnt) ? m : (cnt - 1);
    }
    __syncthreads();

    for (int pass = 3; pass >= 0; pass--) {
        int shift = pass * 8;
        hist[t] = 0u;
        __syncthreads();
        unsigned int pref = s_pref;
        for (int i = t; i < cnt; i += 256) {
            unsigned int key = __float_as_uint(sv[i]);
            if (((key >> shift) >> 8) == pref)
                atomicAdd(&hist[(key >> shift) & 255u], 1u);
        }
        __syncthreads();
        radix_pass(hist, &s_pref, &s_rank, t);
    }

    unsigned int Tkey = s_pref;
    float Tval = __uint_as_float(Tkey);
    int c = 0;
    float ss = 0.0f;
    for (int i = t; i < cnt; i += 256) {
        float v = sv[i];
        if (__float_as_uint(v) < Tkey) { c++; ss += sqrtf(v); }
    }
    s_f[t] = ss; s_i[t] = c;
    __syncthreads();
    for (int off = 128; off > 0; off >>= 1) {
        if (t < off) { s_f[t] += s_f[t + off]; s_i[t] += s_i[t + off]; }
        __syncthreads();
    }
    if (t == 0) {
        double w = (double)s_w;
        double dT = sqrt((double)Tval);
        double cost = w * (double)s_f[0] + (w * (double)(s_m - s_i[0]) + s_r) * dT;
        double BW = 5000.0 / sqrt(128.0);
        out[b] = (float)(5.0 * exp(-BW * cost));
    }
}

// ---------------- launch ----------------
extern "C" void kernel_launch(void* const* d_in, const int* in_sizes, int n_in,
                              void* d_out, int out_size) {
    const float* state   = (const float*)d_in[0];
    const float* action  = (const float*)d_in[1];
    const float* experts = (const float*)d_in[2];
    const float* wts     = (const float*)d_in[3];
    // d_in[4] = scaler_mean: cancels algebraically
    const float* sstd    = (const float*)d_in[5];
    float* out = (float*)d_out;

    cudaFuncSetAttribute(gemm_kernel,   cudaFuncAttributeMaxDynamicSharedMemorySize, GEMM_SMEM);
    cudaFuncSetAttribute(thresh_kernel, cudaFuncAttributeMaxDynamicSharedMemorySize, SAMPLE_N * 4);

    prep_agent_kernel<<<BATCH, DIM>>>(state, action, sstd);
    gemm_kernel<<<dim3(2, STILES), 256, GEMM_SMEM>>>(experts, 0, 0);
    thresh_kernel<<<BATCH, 512, SAMPLE_N * 4>>>();
    gemm_kernel<<<dim3(2, NTILES - STILES), 256, GEMM_SMEM>>>(experts, 1, STILES);
    final_kernel<<<BATCH, 256>>>(wts, out);
}